// round 6
// baseline (speedup 1.0000x reference)
#include <cuda_runtime.h>
#include <math.h>
#include <stdint.h>

// Problem constants
#define B_TOT   4096
#define T_STEPS 25
#define K_ENS   8
#define OBS     64
#define ACT     16
#define IN1     80            // OBS + ACT
#define HID     512
#define OUTD    129           // 2*OBS + 1
#define TM      32            // rows per CTA tile
#define RT_THREADS 512
#define SETUP_THREADS 256
#define MAXTILES 136
#define OUT_STRIDE 132        // padded 129
#define CHK     16            // k-rows per weight chunk

// Dynamic smem layout (floats):
//  sh_x   : TM*IN1        = 2560
//  sh_h1  : TM*HID        = 16384
//  sh_h2  : TM*HID        = 16384
//  sh_out : TM*OUT_STRIDE = 4224
//  sh_w   : 2*CHK*HID     = 16384   (weight double-buffer, 2 x 32KB)
#define SMEM_FLOATS (TM*IN1 + 2*TM*HID + TM*OUT_STRIDE + 2*CHK*HID)
#define SMEM_BYTES  (SMEM_FLOATS * 4)

#define WCHUNK_BYTES   (CHK*HID*4)        // 32768 for layers 1,2
#define W3CHUNK_BYTES  (CHK*OUTD*4)       // 8256 for layer 3

// ---- scratch in device globals (no allocation allowed) ----
__device__ int g_perm[B_TOT];
__device__ int g_tileK[MAXTILES];
__device__ int g_tileStart[MAXTILES];
__device__ int g_tileRows[MAXTILES];
__device__ int g_ntiles;

// ---- packed f32x2 helpers ----
typedef unsigned long long u64;
__device__ __forceinline__ u64 pack_dup(float a) {
    u64 d;
    unsigned int ai = __float_as_uint(a);
    asm("mov.b64 %0, {%1, %1};" : "=l"(d) : "r"(ai));
    return d;
}
__device__ __forceinline__ void fma2(u64& d, u64 a, u64 b, u64 c) {
    asm("fma.rn.f32x2 %0, %1, %2, %3;" : "=l"(d) : "l"(a), "l"(b), "l"(c));
}
__device__ __forceinline__ void unpack2(float& lo, float& hi, u64 v) {
    unsigned int l, h;
    asm("mov.b64 {%0, %1}, %2;" : "=r"(l), "=r"(h) : "l"(v));
    lo = __uint_as_float(l);
    hi = __uint_as_float(h);
}

// ---- mbarrier / bulk-async PTX macros ----
#define MBAR_INIT(addr, cnt) \
    asm volatile("mbarrier.init.shared.b64 [%0], %1;" :: "r"(addr), "r"(cnt) : "memory")
#define MBAR_EXPECT_TX(addr, bytes) \
    asm volatile("mbarrier.arrive.expect_tx.shared.b64 _, [%0], %1;" :: "r"(addr), "r"(bytes) : "memory")
#define MBAR_ARRIVE(addr) \
    asm volatile("mbarrier.arrive.shared.b64 _, [%0];" :: "r"(addr) : "memory")
#define MBAR_WAIT_ACQ(addr, ph) do { unsigned _done = 0; \
    while (!_done) { \
        asm volatile("{\n\t.reg .pred p;\n\t" \
            "mbarrier.try_wait.parity.acquire.cta.shared::cta.b64 p, [%1], %2, 0x989680;\n\t" \
            "selp.b32 %0, 1, 0, p;\n\t}" \
            : "=r"(_done) : "r"(addr), "r"((unsigned)(ph)) : "memory"); \
    } } while (0)
#define MBAR_WAIT_RLX(addr, ph) do { unsigned _done = 0; \
    while (!_done) { \
        asm volatile("{\n\t.reg .pred p;\n\t" \
            "mbarrier.try_wait.parity.relaxed.cta.shared::cta.b64 p, [%1], %2, 0x989680;\n\t" \
            "selp.b32 %0, 1, 0, p;\n\t}" \
            : "=r"(_done) : "r"(addr), "r"((unsigned)(ph)) : "memory"); \
    } } while (0)
#define CP_BULK(dst_smem, src_gmem, bytes, mbar) \
    asm volatile("cp.async.bulk.shared::cluster.global.mbarrier::complete_tx::bytes [%0], [%1], %2, [%3];" \
        :: "r"(dst_smem), "l"(src_gmem), "r"(bytes), "r"(mbar) : "memory")

__device__ __forceinline__ uint32_t smem_u32(const void* p) {
    uint32_t a;
    asm("{ .reg .u64 t; cvta.to.shared.u64 t, %1; cvt.u32.u64 %0, t; }" : "=r"(a) : "l"(p));
    return a;
}

// ============================================================
// Setup: dtype-detect (int32 vs int64) + counting sort by
// ensemble assignment + 32-row tile metadata. One block.
// ============================================================
__global__ void setup_kernel(const int* __restrict__ assign_raw) {
    __shared__ int cnt[K_ENS];
    __shared__ int cur[K_ENS];
    __shared__ int odd_nonzero;
    int tid = threadIdx.x;
    if (tid < K_ENS) cnt[tid] = 0;
    if (tid == 0) odd_nonzero = 0;
    __syncthreads();

    int local_nz = 0;
    for (int w = 2 * tid + 1; w < B_TOT; w += 2 * SETUP_THREADS)
        if (assign_raw[w] != 0) local_nz = 1;
    if (local_nz) atomicOr(&odd_nonzero, 1);
    __syncthreads();
    const bool is_i32 = (odd_nonzero != 0);

    for (int b = tid; b < B_TOT; b += SETUP_THREADS) {
        int k = is_i32 ? assign_raw[b] : assign_raw[2 * b];
        atomicAdd(&cnt[k], 1);
    }
    __syncthreads();
    if (tid == 0) {
        int off = 0, nt = 0;
        for (int k = 0; k < K_ENS; k++) {
            cur[k] = off;
            int c = cnt[k];
            for (int s = 0; s < c; s += TM) {
                g_tileK[nt] = k;
                g_tileStart[nt] = off + s;
                g_tileRows[nt] = (c - s < TM) ? (c - s) : TM;
                nt++;
            }
            off += c;
        }
        g_ntiles = nt;
        for (int e = nt; e < MAXTILES; e++) g_tileRows[e] = 0;
    }
    __syncthreads();
    for (int b = tid; b < B_TOT; b += SETUP_THREADS) {
        int k = is_i32 ? assign_raw[b] : assign_raw[2 * b];
        int pos = atomicAdd(&cur[k], 1);
        g_perm[pos] = b;
    }
}

// ============================================================
// Math helpers
// ============================================================
__device__ __forceinline__ float softplusf(float z) {
    return (z > 0.f) ? (z + log1pf(__expf(-z))) : log1pf(__expf(z));
}
__device__ __forceinline__ float swishf(float x) {
    return x * __frcp_rn(1.f + __expf(-x));
}

// Accumulate one 16-k weight chunk (smem) into packed acc.
// wc: [CHK][512] smem. Thread covers cols tx*4..tx*4+3 (2 packed pairs)
// and 8 rows (ty*8+jr). Activations loaded float4 along k (broadcast).
template<int INSTRIDE>
__device__ __forceinline__ void chunk_dense(
    const float* __restrict__ wc,
    const float* __restrict__ abase,   // sh_in + (ty*8)*INSTRIDE + k0
    u64 acc[8][2], int tx)
{
    const float* wb = wc + tx * 4;
#pragma unroll
    for (int i0 = 0; i0 < CHK; i0 += 4) {
        float4 a4[8];
#pragma unroll
        for (int jr = 0; jr < 8; jr++)
            a4[jr] = *(const float4*)(abase + jr * INSTRIDE + i0);
#pragma unroll
        for (int u = 0; u < 4; u++) {
            ulonglong2 w = *(const ulonglong2*)(wb + (i0 + u) * HID);
            u64 wp0 = w.x, wp1 = w.y;
#pragma unroll
            for (int jr = 0; jr < 8; jr++) {
                float av = (u == 0) ? a4[jr].x : (u == 1) ? a4[jr].y
                         : (u == 2) ? a4[jr].z : a4[jr].w;
                u64 a2 = pack_dup(av);
                fma2(acc[jr][0], a2, wp0, acc[jr][0]);
                fma2(acc[jr][1], a2, wp1, acc[jr][1]);
            }
        }
    }
}

// Accumulate one 16-k chunk of the 129-col output layer.
// wc: [CHK][129] smem. tx3 in 0..31 (cols tx3+32*jc, +128 for tx3==0),
// ty3 in 0..15 (2 rows each).
__device__ __forceinline__ void chunk_out(
    const float* __restrict__ wc,
    const float* __restrict__ abase,   // sh_in + (ty3*2)*HID + k0
    float acc[2][5], int tx3, bool has128)
{
#pragma unroll 4
    for (int i = 0; i < CHK; i++) {
        const float* wr = wc + i * OUTD + tx3;
        float wv[5];
#pragma unroll
        for (int jc = 0; jc < 4; jc++) wv[jc] = wr[jc * 32];
        wv[4] = has128 ? wr[128] : 0.f;
        float a[2];
#pragma unroll
        for (int jr = 0; jr < 2; jr++) a[jr] = abase[jr * HID + i];
#pragma unroll
        for (int jr = 0; jr < 2; jr++)
#pragma unroll
            for (int jc = 0; jc < 5; jc++)
                acc[jr][jc] = fmaf(a[jr], wv[jc], acc[jr][jc]);
    }
}

// ============================================================
// Persistent rollout: one CTA (512 threads) = 32 same-member
// batch rows, all 25 timesteps local; weights double-buffered
// in smem via cp.async.bulk + mbarrier.
// ============================================================
__global__ void __launch_bounds__(RT_THREADS, 1) rollout_kernel(
    const float* __restrict__ obs,
    const float* __restrict__ acts,
    const float* __restrict__ W1, const float* __restrict__ b1,
    const float* __restrict__ W2, const float* __restrict__ b2,
    const float* __restrict__ W3, const float* __restrict__ b3,
    const float* __restrict__ maxlv, const float* __restrict__ minlv,
    const float* __restrict__ noise,
    float* __restrict__ out_obs,
    float* __restrict__ out_rew)
{
    const int tile = blockIdx.x;
    if (tile >= g_ntiles) return;
    const int nrows = g_tileRows[tile];
    const int k     = g_tileK[tile];
    const int start = g_tileStart[tile];

    extern __shared__ float sh[];
    float* sh_x   = sh;                              // [TM][IN1]
    float* sh_h1  = sh_x + TM * IN1;                 // [TM][HID]
    float* sh_h2  = sh_h1 + TM * HID;                // [TM][HID]
    float* sh_out = sh_h2 + TM * HID;                // [TM][OUT_STRIDE]
    float* sh_w   = sh_out + TM * OUT_STRIDE;        // [2][CHK*HID]
    __shared__ int rows[TM];
    __shared__ unsigned long long mb[4];             // full0, full1, empty0, empty1

    const int tid = threadIdx.x;
    const int tx = tid & 127, ty = tid >> 7;         // 128 col-groups x 4 row-groups
    const int tx3 = tid & 31, ty3 = tid >> 5;        // 32 col-groups x 16 row-groups
    const bool has128 = (tx3 == 0);

    const uint32_t mb_base = smem_u32(mb);
    const uint32_t full_a[2]  = {mb_base,      mb_base + 8};
    const uint32_t empty_a[2] = {mb_base + 16, mb_base + 24};
    const uint32_t wbuf_a[2]  = {smem_u32(sh_w), smem_u32(sh_w) + WCHUNK_BYTES};
    const float*   wbuf_p[2]  = {sh_w, sh_w + CHK * HID};

    if (tid < TM) rows[tid] = (tid < nrows) ? g_perm[start + tid] : 0;
    if (tid == 0) {
        MBAR_INIT(full_a[0], 1);
        MBAR_INIT(full_a[1], 1);
        MBAR_INIT(empty_a[0], RT_THREADS);
        MBAR_INIT(empty_a[1], RT_THREADS);
    }

    const float* W1k = W1 + (size_t)k * IN1 * HID;
    const float* W2k = W2 + (size_t)k * HID * HID;
    const float* W3k = W3 + (size_t)k * HID * OUTD;
    const float* b1k = b1 + (size_t)k * HID;
    const float* b2k = b2 + (size_t)k * HID;
    const float* b3k = b3 + (size_t)k * OUTD;

    float bias1[4], bias2[4];
#pragma unroll
    for (int jc = 0; jc < 4; jc++) {
        bias1[jc] = __ldg(b1k + tx * 4 + jc);
        bias2[jc] = __ldg(b2k + tx * 4 + jc);
    }
    float bias3[5];
#pragma unroll
    for (int jc = 0; jc < 4; jc++) bias3[jc] = __ldg(b3k + tx3 + jc * 32);
    bias3[4] = has128 ? __ldg(b3k + 128) : 0.f;

    __syncthreads();   // rows[] + mbarrier init visible

    // ---- pipeline cursors (deterministic, tracked by all threads) ----
    unsigned use_i[2] = {0, 0}; int slot_i = 0;
    unsigned use_c[2] = {0, 0}; int slot_c = 0;

#define ISSUE_CHUNK(srcptr, bytes) do { \
        int _s = slot_i; unsigned _u = use_i[_s]; \
        if (tid == 0) { \
            if (_u >= 1) MBAR_WAIT_RLX(empty_a[_s], (_u - 1) & 1); \
            MBAR_EXPECT_TX(full_a[_s], (unsigned)(bytes)); \
            CP_BULK(wbuf_a[_s], (const char*)(srcptr), (unsigned)(bytes), full_a[_s]); \
        } \
        use_i[_s] = _u + 1; slot_i ^= 1; \
    } while (0)

#define WAIT_FULL(sv) do { sv = slot_c; MBAR_WAIT_ACQ(full_a[sv], use_c[sv] & 1); } while (0)
#define DONE_CHUNK() do { MBAR_ARRIVE(empty_a[slot_c]); use_c[slot_c]++; slot_c ^= 1; } while (0)

    // Init state
    for (int idx = tid; idx < TM * OBS; idx += RT_THREADS) {
        int r = idx >> 6, d = idx & 63;
        sh_x[r * IN1 + d] = (r < nrows) ? obs[(size_t)rows[r] * OBS + d] : 0.f;
    }
    for (int idx = tid; idx < TM * ACT; idx += RT_THREADS) {
        int r = idx >> 4, a = idx & 15;
        sh_x[r * IN1 + OBS + a] = 0.f;
    }

    for (int t = 0; t < T_STEPS; t++) {
        for (int idx = tid; idx < TM * ACT; idx += RT_THREADS) {
            int r = idx >> 4, a = idx & 15;
            if (r < nrows)
                sh_x[r * IN1 + OBS + a] =
                    acts[((size_t)rows[r] * T_STEPS + t) * ACT + a];
        }
        __syncthreads();

        // ================= layer 1: x[80] -> h1[512] =================
        {
            const int NCH = IN1 / CHK;   // 5
            u64 acc[8][2];
#pragma unroll
            for (int jr = 0; jr < 8; jr++) { acc[jr][0] = 0ull; acc[jr][1] = 0ull; }

            ISSUE_CHUNK((const char*)W1k, WCHUNK_BYTES);
            for (int c = 0; c < NCH; c++) {
                if (c + 1 < NCH)
                    ISSUE_CHUNK((const char*)W1k + (size_t)(c + 1) * WCHUNK_BYTES, WCHUNK_BYTES);
                int s; WAIT_FULL(s);
                chunk_dense<IN1>(wbuf_p[s], sh_x + (ty * 8) * IN1 + c * CHK, acc, tx);
                DONE_CHUNK();
            }
#pragma unroll
            for (int jr = 0; jr < 8; jr++) {
                float v0, v1, v2, v3;
                unpack2(v0, v1, acc[jr][0]);
                unpack2(v2, v3, acc[jr][1]);
                v0 = swishf(v0 + bias1[0]); v1 = swishf(v1 + bias1[1]);
                v2 = swishf(v2 + bias1[2]); v3 = swishf(v3 + bias1[3]);
                *(float4*)(sh_h1 + (ty * 8 + jr) * HID + tx * 4) = make_float4(v0, v1, v2, v3);
            }
        }
        __syncthreads();

        // ================= layer 2: h1[512] -> h2[512] =================
        {
            const int NCH = HID / CHK;   // 32
            u64 acc[8][2];
#pragma unroll
            for (int jr = 0; jr < 8; jr++) { acc[jr][0] = 0ull; acc[jr][1] = 0ull; }

            ISSUE_CHUNK((const char*)W2k, WCHUNK_BYTES);
            for (int c = 0; c < NCH; c++) {
                if (c + 1 < NCH)
                    ISSUE_CHUNK((const char*)W2k + (size_t)(c + 1) * WCHUNK_BYTES, WCHUNK_BYTES);
                int s; WAIT_FULL(s);
                chunk_dense<HID>(wbuf_p[s], sh_h1 + (ty * 8) * HID + c * CHK, acc, tx);
                DONE_CHUNK();
            }
#pragma unroll
            for (int jr = 0; jr < 8; jr++) {
                float v0, v1, v2, v3;
                unpack2(v0, v1, acc[jr][0]);
                unpack2(v2, v3, acc[jr][1]);
                v0 = swishf(v0 + bias2[0]); v1 = swishf(v1 + bias2[1]);
                v2 = swishf(v2 + bias2[2]); v3 = swishf(v3 + bias2[3]);
                *(float4*)(sh_h2 + (ty * 8 + jr) * HID + tx * 4) = make_float4(v0, v1, v2, v3);
            }
        }
        __syncthreads();

        // ================= layer 3: h2[512] -> out[129] =================
        {
            const int NCH = HID / CHK;   // 32
            float acc[2][5];
#pragma unroll
            for (int jr = 0; jr < 2; jr++)
#pragma unroll
                for (int jc = 0; jc < 5; jc++) acc[jr][jc] = 0.f;

            ISSUE_CHUNK((const char*)W3k, W3CHUNK_BYTES);
            for (int c = 0; c < NCH; c++) {
                if (c + 1 < NCH)
                    ISSUE_CHUNK((const char*)W3k + (size_t)(c + 1) * W3CHUNK_BYTES, W3CHUNK_BYTES);
                int s; WAIT_FULL(s);
                chunk_out(wbuf_p[s], sh_h2 + (ty3 * 2) * HID + c * CHK, acc, tx3, has128);
                DONE_CHUNK();
            }
#pragma unroll
            for (int jr = 0; jr < 2; jr++) {
#pragma unroll
                for (int jc = 0; jc < 5; jc++) {
                    int col = tx3 + jc * 32;
                    if (col < OUTD)
                        sh_out[(ty3 * 2 + jr) * OUT_STRIDE + col] = acc[jr][jc] + bias3[jc];
                }
            }
        }
        __syncthreads();

        // ================= postprocess =================
        const float* nz_t = noise + ((size_t)t * K_ENS + k) * B_TOT * OBS;
        for (int idx = tid; idx < TM * OBS; idx += RT_THREADS) {
            int r = idx >> 6, d = idx & 63;
            if (r < nrows) {
                int row = rows[r];
                float mean = sh_out[r * OUT_STRIDE + d];
                float lv   = sh_out[r * OUT_STRIDE + OBS + d];
                float mx = __ldg(maxlv + d), mn = __ldg(minlv + d);
                lv = mx - softplusf(mx - lv);
                lv = mn + softplusf(lv - mn);
                float nz = __ldg(nz_t + (size_t)row * OBS + d);
                float no = fmaf(nz, __expf(0.5f * lv), mean);
                out_obs[((size_t)row * T_STEPS + t) * OBS + d] = no;
                sh_x[r * IN1 + d] = no;
            }
        }
        if (tid < nrows)
            out_rew[(size_t)rows[tid] * T_STEPS + t] = sh_out[tid * OUT_STRIDE + 128];
        __syncthreads();
    }
#undef ISSUE_CHUNK
#undef WAIT_FULL
#undef DONE_CHUNK
}

// ============================================================
// Launch
// ============================================================
extern "C" void kernel_launch(void* const* d_in, const int* in_sizes, int n_in,
                              void* d_out, int out_size) {
    const float* obs   = (const float*)d_in[0];
    const float* acts  = (const float*)d_in[1];
    const float* W1    = (const float*)d_in[2];
    const float* b1    = (const float*)d_in[3];
    const float* W2    = (const float*)d_in[4];
    const float* b2    = (const float*)d_in[5];
    const float* W3    = (const float*)d_in[6];
    const float* b3    = (const float*)d_in[7];
    const float* maxlv = (const float*)d_in[8];
    const float* minlv = (const float*)d_in[9];
    const float* noise = (const float*)d_in[10];
    const int*   assign_raw = (const int*)d_in[11];

    float* out_obs = (float*)d_out;
    float* out_rew = out_obs + (size_t)B_TOT * T_STEPS * OBS;

    cudaFuncSetAttribute(rollout_kernel,
                         cudaFuncAttributeMaxDynamicSharedMemorySize, SMEM_BYTES);

    setup_kernel<<<1, SETUP_THREADS>>>(assign_raw);
    rollout_kernel<<<MAXTILES, RT_THREADS, SMEM_BYTES>>>(
        obs, acts, W1, b1, W2, b2, W3, b3, maxlv, minlv, noise,
        out_obs, out_rew);
}

// round 7
// speedup vs baseline: 1.0163x; 1.0163x over previous
#include <cuda_runtime.h>
#include <math.h>
#include <stdint.h>

// Problem constants
#define B_TOT   4096
#define T_STEPS 25
#define K_ENS   8
#define OBS     64
#define ACT     16
#define IN1     80            // OBS + ACT
#define HID     512
#define OUTD    129           // 2*OBS + 1
#define TM      32            // rows per CTA tile
#define RT_THREADS 512
#define SETUP_THREADS 256
#define MAXTILES 136
#define OUT_STRIDE 132        // padded 129
#define CHK     16            // k-rows per weight chunk

// Dynamic smem layout (floats):
//  sh_x   : TM*IN1        = 2560
//  sh_h1  : TM*HID        = 16384
//  sh_h2  : TM*HID        = 16384
//  sh_out : TM*OUT_STRIDE = 4224
//  sh_w   : 2*CHK*HID     = 16384   (weight double-buffer, 2 x 32KB)
#define SMEM_FLOATS (TM*IN1 + 2*TM*HID + TM*OUT_STRIDE + 2*CHK*HID)
#define SMEM_BYTES  (SMEM_FLOATS * 4)

#define WCHUNK_BYTES   (CHK*HID*4)        // 32768 for layers 1,2
#define W3CHUNK_BYTES  (CHK*OUTD*4)       // 8256 for layer 3

// ---- scratch in device globals (no allocation allowed) ----
__device__ int g_perm[B_TOT];
__device__ int g_tileK[MAXTILES];
__device__ int g_tileStart[MAXTILES];
__device__ int g_tileRows[MAXTILES];
__device__ int g_ntiles;

// ---- packed f32x2 helpers ----
typedef unsigned long long u64;
__device__ __forceinline__ u64 pack_dup(float a) {
    u64 d;
    unsigned int ai = __float_as_uint(a);
    asm("mov.b64 %0, {%1, %1};" : "=l"(d) : "r"(ai));
    return d;
}
__device__ __forceinline__ void fma2(u64& d, u64 a, u64 b, u64 c) {
    asm("fma.rn.f32x2 %0, %1, %2, %3;" : "=l"(d) : "l"(a), "l"(b), "l"(c));
}
__device__ __forceinline__ void unpack2(float& lo, float& hi, u64 v) {
    unsigned int l, h;
    asm("mov.b64 {%0, %1}, %2;" : "=r"(l), "=r"(h) : "l"(v));
    lo = __uint_as_float(l);
    hi = __uint_as_float(h);
}

// ---- mbarrier / bulk-async PTX macros ----
#define MBAR_INIT(addr, cnt) \
    asm volatile("mbarrier.init.shared.b64 [%0], %1;" :: "r"(addr), "r"(cnt) : "memory")
#define MBAR_EXPECT_TX(addr, bytes) \
    asm volatile("mbarrier.arrive.expect_tx.shared.b64 _, [%0], %1;" :: "r"(addr), "r"(bytes) : "memory")
#define MBAR_ARRIVE(addr) \
    asm volatile("mbarrier.arrive.shared.b64 _, [%0];" :: "r"(addr) : "memory")
#define MBAR_WAIT_ACQ(addr, ph) do { unsigned _done = 0; \
    while (!_done) { \
        asm volatile("{\n\t.reg .pred p;\n\t" \
            "mbarrier.try_wait.parity.acquire.cta.shared::cta.b64 p, [%1], %2, 0x989680;\n\t" \
            "selp.b32 %0, 1, 0, p;\n\t}" \
            : "=r"(_done) : "r"(addr), "r"((unsigned)(ph)) : "memory"); \
    } } while (0)
#define MBAR_WAIT_RLX(addr, ph) do { unsigned _done = 0; \
    while (!_done) { \
        asm volatile("{\n\t.reg .pred p;\n\t" \
            "mbarrier.try_wait.parity.relaxed.cta.shared::cta.b64 p, [%1], %2, 0x989680;\n\t" \
            "selp.b32 %0, 1, 0, p;\n\t}" \
            : "=r"(_done) : "r"(addr), "r"((unsigned)(ph)) : "memory"); \
    } } while (0)
#define CP_BULK(dst_smem, src_gmem, bytes, mbar) \
    asm volatile("cp.async.bulk.shared::cluster.global.mbarrier::complete_tx::bytes [%0], [%1], %2, [%3];" \
        :: "r"(dst_smem), "l"(src_gmem), "r"(bytes), "r"(mbar) : "memory")

__device__ __forceinline__ uint32_t smem_u32(const void* p) {
    uint32_t a;
    asm("{ .reg .u64 t; cvta.to.shared.u64 t, %1; cvt.u32.u64 %0, t; }" : "=r"(a) : "l"(p));
    return a;
}

// ============================================================
// Setup: dtype-detect (int32 vs int64) + counting sort by
// ensemble assignment + 32-row tile metadata. One block.
// ============================================================
__global__ void setup_kernel(const int* __restrict__ assign_raw) {
    __shared__ int cnt[K_ENS];
    __shared__ int cur[K_ENS];
    __shared__ int odd_nonzero;
    int tid = threadIdx.x;
    if (tid < K_ENS) cnt[tid] = 0;
    if (tid == 0) odd_nonzero = 0;
    __syncthreads();

    int local_nz = 0;
    for (int w = 2 * tid + 1; w < B_TOT; w += 2 * SETUP_THREADS)
        if (assign_raw[w] != 0) local_nz = 1;
    if (local_nz) atomicOr(&odd_nonzero, 1);
    __syncthreads();
    const bool is_i32 = (odd_nonzero != 0);

    for (int b = tid; b < B_TOT; b += SETUP_THREADS) {
        int k = is_i32 ? assign_raw[b] : assign_raw[2 * b];
        atomicAdd(&cnt[k], 1);
    }
    __syncthreads();
    if (tid == 0) {
        int off = 0, nt = 0;
        for (int k = 0; k < K_ENS; k++) {
            cur[k] = off;
            int c = cnt[k];
            for (int s = 0; s < c; s += TM) {
                g_tileK[nt] = k;
                g_tileStart[nt] = off + s;
                g_tileRows[nt] = (c - s < TM) ? (c - s) : TM;
                nt++;
            }
            off += c;
        }
        g_ntiles = nt;
        for (int e = nt; e < MAXTILES; e++) g_tileRows[e] = 0;
    }
    __syncthreads();
    for (int b = tid; b < B_TOT; b += SETUP_THREADS) {
        int k = is_i32 ? assign_raw[b] : assign_raw[2 * b];
        int pos = atomicAdd(&cur[k], 1);
        g_perm[pos] = b;
    }
}

// ============================================================
// Math helpers
// ============================================================
__device__ __forceinline__ float softplusf(float z) {
    return (z > 0.f) ? (z + log1pf(__expf(-z))) : log1pf(__expf(z));
}
__device__ __forceinline__ float swishf(float x) {
    return x * __frcp_rn(1.f + __expf(-x));
}

// Accumulate one 16-k weight chunk (smem) into packed acc.
// wc: [CHK][512] smem. Thread covers cols tx*4..tx*4+3 (2 packed pairs)
// and 8 rows (ty*8+jr). Activations loaded float4 along k (broadcast).
template<int INSTRIDE>
__device__ __forceinline__ void chunk_dense(
    const float* __restrict__ wc,
    const float* __restrict__ abase,   // sh_in + (ty*8)*INSTRIDE + k0
    u64 acc[8][2], int tx)
{
    const float* wb = wc + tx * 4;
#pragma unroll
    for (int i0 = 0; i0 < CHK; i0 += 4) {
        float4 a4[8];
#pragma unroll
        for (int jr = 0; jr < 8; jr++)
            a4[jr] = *(const float4*)(abase + jr * INSTRIDE + i0);
#pragma unroll
        for (int u = 0; u < 4; u++) {
            ulonglong2 w = *(const ulonglong2*)(wb + (i0 + u) * HID);
            u64 wp0 = w.x, wp1 = w.y;
#pragma unroll
            for (int jr = 0; jr < 8; jr++) {
                float av = (u == 0) ? a4[jr].x : (u == 1) ? a4[jr].y
                         : (u == 2) ? a4[jr].z : a4[jr].w;
                u64 a2 = pack_dup(av);
                fma2(acc[jr][0], a2, wp0, acc[jr][0]);
                fma2(acc[jr][1], a2, wp1, acc[jr][1]);
            }
        }
    }
}

// Accumulate one 16-k chunk of the 129-col output layer.
// wc: [CHK][129] smem. tx3 in 0..31 (cols tx3+32*jc, +128 for tx3==0),
// ty3 in 0..15 (2 rows each).
__device__ __forceinline__ void chunk_out(
    const float* __restrict__ wc,
    const float* __restrict__ abase,   // sh_in + (ty3*2)*HID + k0
    float acc[2][5], int tx3, bool has128)
{
#pragma unroll 4
    for (int i = 0; i < CHK; i++) {
        const float* wr = wc + i * OUTD + tx3;
        float wv[5];
#pragma unroll
        for (int jc = 0; jc < 4; jc++) wv[jc] = wr[jc * 32];
        wv[4] = has128 ? wr[128] : 0.f;
        float a[2];
#pragma unroll
        for (int jr = 0; jr < 2; jr++) a[jr] = abase[jr * HID + i];
#pragma unroll
        for (int jr = 0; jr < 2; jr++)
#pragma unroll
            for (int jc = 0; jc < 5; jc++)
                acc[jr][jc] = fmaf(a[jr], wv[jc], acc[jr][jc]);
    }
}

// ============================================================
// Persistent rollout: one CTA (512 threads) = 32 same-member
// batch rows, all 25 timesteps local; weights double-buffered
// in smem via cp.async.bulk + mbarrier.
// ============================================================
__global__ void __launch_bounds__(RT_THREADS, 1) rollout_kernel(
    const float* __restrict__ obs,
    const float* __restrict__ acts,
    const float* __restrict__ W1, const float* __restrict__ b1,
    const float* __restrict__ W2, const float* __restrict__ b2,
    const float* __restrict__ W3, const float* __restrict__ b3,
    const float* __restrict__ maxlv, const float* __restrict__ minlv,
    const float* __restrict__ noise,
    float* __restrict__ out_obs,
    float* __restrict__ out_rew)
{
    const int tile = blockIdx.x;
    if (tile >= g_ntiles) return;
    const int nrows = g_tileRows[tile];
    const int k     = g_tileK[tile];
    const int start = g_tileStart[tile];

    extern __shared__ float sh[];
    float* sh_x   = sh;                              // [TM][IN1]
    float* sh_h1  = sh_x + TM * IN1;                 // [TM][HID]
    float* sh_h2  = sh_h1 + TM * HID;                // [TM][HID]
    float* sh_out = sh_h2 + TM * HID;                // [TM][OUT_STRIDE]
    float* sh_w   = sh_out + TM * OUT_STRIDE;        // [2][CHK*HID]
    __shared__ int rows[TM];
    __shared__ unsigned long long mb[4];             // full0, full1, empty0, empty1

    const int tid = threadIdx.x;
    const int tx = tid & 127, ty = tid >> 7;         // 128 col-groups x 4 row-groups
    const int tx3 = tid & 31, ty3 = tid >> 5;        // 32 col-groups x 16 row-groups
    const bool has128 = (tx3 == 0);

    const uint32_t mb_base = smem_u32(mb);
    const uint32_t full_a[2]  = {mb_base,      mb_base + 8};
    const uint32_t empty_a[2] = {mb_base + 16, mb_base + 24};
    const uint32_t wbuf_a[2]  = {smem_u32(sh_w), smem_u32(sh_w) + WCHUNK_BYTES};
    const float*   wbuf_p[2]  = {sh_w, sh_w + CHK * HID};

    if (tid < TM) rows[tid] = (tid < nrows) ? g_perm[start + tid] : 0;
    if (tid == 0) {
        MBAR_INIT(full_a[0], 1);
        MBAR_INIT(full_a[1], 1);
        MBAR_INIT(empty_a[0], RT_THREADS);
        MBAR_INIT(empty_a[1], RT_THREADS);
    }

    const float* W1k = W1 + (size_t)k * IN1 * HID;
    const float* W2k = W2 + (size_t)k * HID * HID;
    const float* W3k = W3 + (size_t)k * HID * OUTD;
    const float* b1k = b1 + (size_t)k * HID;
    const float* b2k = b2 + (size_t)k * HID;
    const float* b3k = b3 + (size_t)k * OUTD;

    float bias1[4], bias2[4];
#pragma unroll
    for (int jc = 0; jc < 4; jc++) {
        bias1[jc] = __ldg(b1k + tx * 4 + jc);
        bias2[jc] = __ldg(b2k + tx * 4 + jc);
    }
    float bias3[5];
#pragma unroll
    for (int jc = 0; jc < 4; jc++) bias3[jc] = __ldg(b3k + tx3 + jc * 32);
    bias3[4] = has128 ? __ldg(b3k + 128) : 0.f;

    __syncthreads();   // rows[] + mbarrier init visible

    // ---- pipeline cursors (deterministic, tracked by all threads) ----
    unsigned use_i[2] = {0, 0}; int slot_i = 0;
    unsigned use_c[2] = {0, 0}; int slot_c = 0;

#define ISSUE_CHUNK(srcptr, bytes) do { \
        int _s = slot_i; unsigned _u = use_i[_s]; \
        if (tid == 0) { \
            if (_u >= 1) MBAR_WAIT_RLX(empty_a[_s], (_u - 1) & 1); \
            MBAR_EXPECT_TX(full_a[_s], (unsigned)(bytes)); \
            CP_BULK(wbuf_a[_s], (const char*)(srcptr), (unsigned)(bytes), full_a[_s]); \
        } \
        use_i[_s] = _u + 1; slot_i ^= 1; \
    } while (0)

#define WAIT_FULL(sv) do { sv = slot_c; MBAR_WAIT_ACQ(full_a[sv], use_c[sv] & 1); } while (0)
#define DONE_CHUNK() do { MBAR_ARRIVE(empty_a[slot_c]); use_c[slot_c]++; slot_c ^= 1; } while (0)

    // Init state
    for (int idx = tid; idx < TM * OBS; idx += RT_THREADS) {
        int r = idx >> 6, d = idx & 63;
        sh_x[r * IN1 + d] = (r < nrows) ? obs[(size_t)rows[r] * OBS + d] : 0.f;
    }
    for (int idx = tid; idx < TM * ACT; idx += RT_THREADS) {
        int r = idx >> 4, a = idx & 15;
        sh_x[r * IN1 + OBS + a] = 0.f;
    }

    for (int t = 0; t < T_STEPS; t++) {
        for (int idx = tid; idx < TM * ACT; idx += RT_THREADS) {
            int r = idx >> 4, a = idx & 15;
            if (r < nrows)
                sh_x[r * IN1 + OBS + a] =
                    acts[((size_t)rows[r] * T_STEPS + t) * ACT + a];
        }
        __syncthreads();

        // ================= layer 1: x[80] -> h1[512] =================
        {
            const int NCH = IN1 / CHK;   // 5
            u64 acc[8][2];
#pragma unroll
            for (int jr = 0; jr < 8; jr++) { acc[jr][0] = 0ull; acc[jr][1] = 0ull; }

            ISSUE_CHUNK((const char*)W1k, WCHUNK_BYTES);
            for (int c = 0; c < NCH; c++) {
                if (c + 1 < NCH)
                    ISSUE_CHUNK((const char*)W1k + (size_t)(c + 1) * WCHUNK_BYTES, WCHUNK_BYTES);
                int s; WAIT_FULL(s);
                chunk_dense<IN1>(wbuf_p[s], sh_x + (ty * 8) * IN1 + c * CHK, acc, tx);
                DONE_CHUNK();
            }
#pragma unroll
            for (int jr = 0; jr < 8; jr++) {
                float v0, v1, v2, v3;
                unpack2(v0, v1, acc[jr][0]);
                unpack2(v2, v3, acc[jr][1]);
                v0 = swishf(v0 + bias1[0]); v1 = swishf(v1 + bias1[1]);
                v2 = swishf(v2 + bias1[2]); v3 = swishf(v3 + bias1[3]);
                *(float4*)(sh_h1 + (ty * 8 + jr) * HID + tx * 4) = make_float4(v0, v1, v2, v3);
            }
        }
        __syncthreads();

        // ================= layer 2: h1[512] -> h2[512] =================
        {
            const int NCH = HID / CHK;   // 32
            u64 acc[8][2];
#pragma unroll
            for (int jr = 0; jr < 8; jr++) { acc[jr][0] = 0ull; acc[jr][1] = 0ull; }

            ISSUE_CHUNK((const char*)W2k, WCHUNK_BYTES);
            for (int c = 0; c < NCH; c++) {
                if (c + 1 < NCH)
                    ISSUE_CHUNK((const char*)W2k + (size_t)(c + 1) * WCHUNK_BYTES, WCHUNK_BYTES);
                int s; WAIT_FULL(s);
                chunk_dense<HID>(wbuf_p[s], sh_h1 + (ty * 8) * HID + c * CHK, acc, tx);
                DONE_CHUNK();
            }
#pragma unroll
            for (int jr = 0; jr < 8; jr++) {
                float v0, v1, v2, v3;
                unpack2(v0, v1, acc[jr][0]);
                unpack2(v2, v3, acc[jr][1]);
                v0 = swishf(v0 + bias2[0]); v1 = swishf(v1 + bias2[1]);
                v2 = swishf(v2 + bias2[2]); v3 = swishf(v3 + bias2[3]);
                *(float4*)(sh_h2 + (ty * 8 + jr) * HID + tx * 4) = make_float4(v0, v1, v2, v3);
            }
        }
        __syncthreads();

        // ================= layer 3: h2[512] -> out[129] =================
        {
            const int NCH = HID / CHK;   // 32
            float acc[2][5];
#pragma unroll
            for (int jr = 0; jr < 2; jr++)
#pragma unroll
                for (int jc = 0; jc < 5; jc++) acc[jr][jc] = 0.f;

            ISSUE_CHUNK((const char*)W3k, W3CHUNK_BYTES);
            for (int c = 0; c < NCH; c++) {
                if (c + 1 < NCH)
                    ISSUE_CHUNK((const char*)W3k + (size_t)(c + 1) * W3CHUNK_BYTES, W3CHUNK_BYTES);
                int s; WAIT_FULL(s);
                chunk_out(wbuf_p[s], sh_h2 + (ty3 * 2) * HID + c * CHK, acc, tx3, has128);
                DONE_CHUNK();
            }
#pragma unroll
            for (int jr = 0; jr < 2; jr++) {
#pragma unroll
                for (int jc = 0; jc < 5; jc++) {
                    int col = tx3 + jc * 32;
                    if (col < OUTD)
                        sh_out[(ty3 * 2 + jr) * OUT_STRIDE + col] = acc[jr][jc] + bias3[jc];
                }
            }
        }
        __syncthreads();

        // ================= postprocess =================
        const float* nz_t = noise + ((size_t)t * K_ENS + k) * B_TOT * OBS;
        for (int idx = tid; idx < TM * OBS; idx += RT_THREADS) {
            int r = idx >> 6, d = idx & 63;
            if (r < nrows) {
                int row = rows[r];
                float mean = sh_out[r * OUT_STRIDE + d];
                float lv   = sh_out[r * OUT_STRIDE + OBS + d];
                float mx = __ldg(maxlv + d), mn = __ldg(minlv + d);
                lv = mx - softplusf(mx - lv);
                lv = mn + softplusf(lv - mn);
                float nz = __ldg(nz_t + (size_t)row * OBS + d);
                float no = fmaf(nz, __expf(0.5f * lv), mean);
                out_obs[((size_t)row * T_STEPS + t) * OBS + d] = no;
                sh_x[r * IN1 + d] = no;
            }
        }
        if (tid < nrows)
            out_rew[(size_t)rows[tid] * T_STEPS + t] = sh_out[tid * OUT_STRIDE + 128];
        __syncthreads();
    }
#undef ISSUE_CHUNK
#undef WAIT_FULL
#undef DONE_CHUNK
}

// ============================================================
// Launch
// ============================================================
extern "C" void kernel_launch(void* const* d_in, const int* in_sizes, int n_in,
                              void* d_out, int out_size) {
    const float* obs   = (const float*)d_in[0];
    const float* acts  = (const float*)d_in[1];
    const float* W1    = (const float*)d_in[2];
    const float* b1    = (const float*)d_in[3];
    const float* W2    = (const float*)d_in[4];
    const float* b2    = (const float*)d_in[5];
    const float* W3    = (const float*)d_in[6];
    const float* b3    = (const float*)d_in[7];
    const float* maxlv = (const float*)d_in[8];
    const float* minlv = (const float*)d_in[9];
    const float* noise = (const float*)d_in[10];
    const int*   assign_raw = (const int*)d_in[11];

    float* out_obs = (float*)d_out;
    float* out_rew = out_obs + (size_t)B_TOT * T_STEPS * OBS;

    cudaFuncSetAttribute(rollout_kernel,
                         cudaFuncAttributeMaxDynamicSharedMemorySize, SMEM_BYTES);

    setup_kernel<<<1, SETUP_THREADS>>>(assign_raw);
    rollout_kernel<<<MAXTILES, RT_THREADS, SMEM_BYTES>>>(
        obs, acts, W1, b1, W2, b2, W3, b3, maxlv, minlv, noise,
        out_obs, out_rew);
}